// round 2
// baseline (speedup 1.0000x reference)
#include <cuda_runtime.h>
#include <cstdint>

typedef unsigned long long ull;

// Packed fp32x2 FMA (sm_100+/sm_103a; ptxas never auto-generates this)
#define FMA2(d, a, b, c) \
    asm("fma.rn.f32x2 %0, %1, %2, %3;" : "=l"(d) : "l"(a), "l"(b), "l"(c))
#define ADD2(d, a, b) \
    asm("add.rn.f32x2 %0, %1, %2;" : "=l"(d) : "l"(a), "l"(b))

__device__ __forceinline__ ull pack2(float lo, float hi) {
    ull r; asm("mov.b64 %0, {%1, %2};" : "=l"(r) : "f"(lo), "f"(hi)); return r;
}
__device__ __forceinline__ void unpack2(ull v, float& lo, float& hi) {
    asm("mov.b64 {%0, %1}, %2;" : "=f"(lo), "=f"(hi) : "l"(v));
}

// Problem constants
constexpr int B  = 8;
constexpr int C  = 256;
constexpr int M  = 64;
constexpr int H  = 128, W = 128, HW = H * W;       // input spatial
constexpr int KK = 25;                              // 5x5 window
constexpr int nH = 64, nW = 64, nHW = nH * nW;      // output spatial

// Scratch (device globals — no allocation allowed)
__device__ float g_mid[(size_t)B * M * HW];    // conv1x1 output (33.5 MB)
__device__ float g_ker[(size_t)B * KK * nHW];  // softmax kernel (3.3 MB)

// ---------------------------------------------------------------------------
// Kernel 1: 1x1 conv  C=256 -> M=64, + bias.  GEMM [64,256] x [256, B*HW].
// Block: 256 threads, tile = 128 pixels x 64 m-channels.
// Accumulators are f32x2 pairs over adjacent pixels; weights pre-splatted.
// ---------------------------------------------------------------------------
__global__ void __launch_bounds__(256) k1_conv1x1(
    const float* __restrict__ x, const float* __restrict__ w1,
    const float* __restrict__ b1)
{
    __shared__ float2 wt[32][66];   // wt[c][m] = (w, w) splat pairs (padded)
    __shared__ float  xs[32][128];  // xs[c][p]

    const int t  = threadIdx.x;
    const int b  = blockIdx.y;
    const int p0 = blockIdx.x * 128;
    const int mg = t & 7,  pg = t >> 3;
    const int mb = mg * 8, pb = pg * 4;

    ull acc[8][2];
#pragma unroll
    for (int i = 0; i < 8; i++) { acc[i][0] = 0ULL; acc[i][1] = 0ULL; }

    for (int ch = 0; ch < 8; ch++) {
        const int c0 = ch * 32;
        // load weight chunk, transposed + splatted
        {
            const int cc = t & 31;
            const int mr = t >> 5;  // 0..7
#pragma unroll
            for (int i = 0; i < 8; i++) {
                const int m = i * 8 + mr;
                float wv = w1[m * C + c0 + cc];
                wt[cc][m] = make_float2(wv, wv);
            }
        }
        // load x chunk (coalesced rows)
#pragma unroll
        for (int j = 0; j < 16; j++) {
            int idx = j * 256 + t;
            int cc = idx >> 7, p = idx & 127;
            xs[cc][p] = x[((size_t)(b * C + c0 + cc)) * HW + p0 + p];
        }
        __syncthreads();
#pragma unroll
        for (int cc = 0; cc < 32; cc++) {
            ulonglong2 xv = *(const ulonglong2*)&xs[cc][pb];
#pragma unroll
            for (int i = 0; i < 4; i++) {
                ulonglong2 wv = *(const ulonglong2*)&wt[cc][mb + 2 * i];
                FMA2(acc[2*i  ][0], wv.x, xv.x, acc[2*i  ][0]);
                FMA2(acc[2*i  ][1], wv.x, xv.y, acc[2*i  ][1]);
                FMA2(acc[2*i+1][0], wv.y, xv.x, acc[2*i+1][0]);
                FMA2(acc[2*i+1][1], wv.y, xv.y, acc[2*i+1][1]);
            }
        }
        __syncthreads();
    }

#pragma unroll
    for (int i = 0; i < 8; i++) {
        const int m = mb + i;
        const float bias = b1[m];
        float o0, o1, o2, o3;
        unpack2(acc[i][0], o0, o1);
        unpack2(acc[i][1], o2, o3);
        float4 r = make_float4(o0 + bias, o1 + bias, o2 + bias, o3 + bias);
        *(float4*)&g_mid[((size_t)(b * M + m)) * HW + p0 + pb] = r;
    }
}

// ---------------------------------------------------------------------------
// Kernel 2: 3x3 conv stride 2 pad 1, M=64 -> 25, + bias, + softmax over 25.
// Channel-pair f32x2: lane0 accumulates channel c, lane1 channel c+1
// (interleaved smem tiles + interleaved weight pairs). One output px/thread.
// Tile: 16 (w) x 8 (h) outputs per block, 128 threads.
// ---------------------------------------------------------------------------
__global__ void __launch_bounds__(128) k2_encoder(
    const float* __restrict__ w2, const float* __restrict__ b2)
{
    __shared__ float2 ms[2][17][37];   // [cpair][row][col] = (mid_c, mid_c+1)
    __shared__ float2 ws[2][9][26];    // [cpair][j][k]     = (w2[k][c][j], w2[k][c+1][j])

    const int t  = threadIdx.x;
    const int b  = blockIdx.z;
    const int h0 = blockIdx.y * 8;
    const int w0 = blockIdx.x * 16;
    const int ty = t >> 4;   // 0..7
    const int tx = t & 15;   // 0..15

    ull acc[25];
#pragma unroll
    for (int k = 0; k < 25; k++) acc[k] = 0ULL;

    for (int chk = 0; chk < 16; chk++) {
        const int c0 = chk * 4;
        // weights: 2 cpairs x 9 x 25
        for (int idx = t; idx < 450; idx += 128) {
            int cp = idx / 225, r = idx % 225;
            int j = r / 25, k = r % 25;
            int c = c0 + 2 * cp;
            ws[cp][j][k] = make_float2(w2[(k * M + c    ) * 9 + j],
                                       w2[(k * M + c + 1) * 9 + j]);
        }
        // mid tile: rows 2h0-1 .. 2h0+15 (17), cols 2w0-1 .. 2w0+31 (33)
        for (int idx = t; idx < 2 * 17 * 33; idx += 128) {
            int cp = idx / 561, r = idx % 561;
            int i = r / 33, jj = r % 33;
            int ih = 2 * h0 - 1 + i, iw = 2 * w0 - 1 + jj;
            float v0 = 0.f, v1 = 0.f;
            if ((unsigned)ih < 128u && (unsigned)iw < 128u) {
                size_t base = ((size_t)(b * M + c0 + 2 * cp)) * HW + ih * W + iw;
                v0 = g_mid[base];
                v1 = g_mid[base + HW];
            }
            ms[cp][i][jj] = make_float2(v0, v1);
        }
        __syncthreads();
#pragma unroll
        for (int cp = 0; cp < 2; cp++) {
            ull xp[9];
#pragma unroll
            for (int i = 0; i < 3; i++)
#pragma unroll
                for (int j = 0; j < 3; j++)
                    xp[i * 3 + j] = *(const ull*)&ms[cp][2 * ty + i][2 * tx + j];
#pragma unroll
            for (int j9 = 0; j9 < 9; j9++) {
#pragma unroll
                for (int k2 = 0; k2 < 12; k2++) {
                    ulonglong2 wq = *(const ulonglong2*)&ws[cp][j9][2 * k2];
                    FMA2(acc[2*k2  ], wq.x, xp[j9], acc[2*k2  ]);
                    FMA2(acc[2*k2+1], wq.y, xp[j9], acc[2*k2+1]);
                }
                ull wl = *(const ull*)&ws[cp][j9][24];
                FMA2(acc[24], wl, xp[j9], acc[24]);
            }
        }
        __syncthreads();
    }

    // combine lanes, bias, softmax over 25, store
    float lg[25];
#pragma unroll
    for (int k = 0; k < 25; k++) {
        float a, bq; unpack2(acc[k], a, bq);
        lg[k] = a + bq + b2[k];
    }
    float mx = lg[0];
#pragma unroll
    for (int k = 1; k < 25; k++) mx = fmaxf(mx, lg[k]);
    float e[25], s = 0.f;
#pragma unroll
    for (int k = 0; k < 25; k++) { e[k] = __expf(lg[k] - mx); s += e[k]; }
    const float inv = 1.f / s;
    const int h = h0 + ty, w = w0 + tx;
    const size_t base = ((size_t)b * KK) * nHW + h * nW + w;
#pragma unroll
    for (int k = 0; k < 25; k++)
        g_ker[base + (size_t)k * nHW] = e[k] * inv;
}

// ---------------------------------------------------------------------------
// Kernel 3: softmax-weighted 5x5 window sum over x (stride 2, pad 2).
// Channel-pair f32x2: xi smem holds (x_c, x_{c+1}) interleaved; ker weights
// splatted in registers. 16x16 output tile, 256 threads, 128 channels/block.
// ---------------------------------------------------------------------------
__global__ void __launch_bounds__(256) k3_apply(
    const float* __restrict__ x, float* __restrict__ out)
{
    __shared__ float2 xi[35][37];

    const int t  = threadIdx.x;
    const int bz = blockIdx.z;
    const int b  = bz >> 1;
    const int cbase = (bz & 1) * 128;
    const int h0 = blockIdx.y * 16, w0 = blockIdx.x * 16;
    const int py = t >> 4, px = t & 15;
    const int h = h0 + py, w = w0 + px;

    // per-pixel softmax weights, splatted into pairs
    ull kp[25];
#pragma unroll
    for (int k = 0; k < 25; k++) {
        float kv = g_ker[((size_t)(b * KK + k)) * nHW + h * nW + w];
        kp[k] = pack2(kv, kv);
    }

    const int ir0 = 2 * h0 - 2, ic0 = 2 * w0 - 2;

    for (int c = cbase; c < cbase + 128; c += 2) {
        __syncthreads();
        const float* xc0 = x + ((size_t)(b * C + c)) * HW;
        for (int idx = t; idx < 35 * 35; idx += 256) {
            int r = idx / 35, cc = idx % 35;
            int ir = ir0 + r, ic = ic0 + cc;
            float v0 = 0.f, v1 = 0.f;
            if ((unsigned)ir < 128u && (unsigned)ic < 128u) {
                v0 = xc0[ir * W + ic];
                v1 = xc0[HW + ir * W + ic];
            }
            xi[r][cc] = make_float2(v0, v1);
        }
        __syncthreads();

        ull a[5];
#pragma unroll
        for (int i = 0; i < 5; i++) a[i] = 0ULL;
#pragma unroll
        for (int i = 0; i < 5; i++)
#pragma unroll
            for (int j = 0; j < 5; j++) {
                ull xv = *(const ull*)&xi[2 * py + i][2 * px + j];
                const int k = i * 5 + j;
                FMA2(a[k % 5], kp[k], xv, a[k % 5]);
            }
        ull s01, s23, s;
        ADD2(s01, a[0], a[1]);
        ADD2(s23, a[2], a[3]);
        ADD2(s01, s01, s23);
        ADD2(s, s01, a[4]);
        float o0, o1; unpack2(s, o0, o1);
        const size_t obase = ((size_t)(b * C + c)) * nHW + h * nW + w;
        out[obase]       = o0;
        out[obase + nHW] = o1;
    }
}

// ---------------------------------------------------------------------------
extern "C" void kernel_launch(void* const* d_in, const int* in_sizes, int n_in,
                              void* d_out, int out_size)
{
    (void)in_sizes; (void)n_in; (void)out_size;
    const float* x  = (const float*)d_in[0];
    const float* w1 = (const float*)d_in[1];
    const float* b1 = (const float*)d_in[2];
    const float* w2 = (const float*)d_in[3];
    const float* b2 = (const float*)d_in[4];
    float* out = (float*)d_out;

    k1_conv1x1<<<dim3(128, 8), 256>>>(x, w1, b1);        // mid = conv1x1(x)+b1
    k2_encoder<<<dim3(4, 8, 8), 128>>>(w2, b2);          // ker = softmax(conv3x3(mid)+b2)
    k3_apply<<<dim3(4, 4, 16), 256>>>(x, out);           // out = weighted window sum
}

// round 3
// speedup vs baseline: 1.4813x; 1.4813x over previous
#include <cuda_runtime.h>
#include <cstdint>

typedef unsigned long long ull;

// Packed fp32x2 FMA (sm_100+/sm_103a; ptxas never auto-generates this)
#define FMA2(d, a, b, c) \
    asm("fma.rn.f32x2 %0, %1, %2, %3;" : "=l"(d) : "l"(a), "l"(b), "l"(c))
#define ADD2(d, a, b) \
    asm("add.rn.f32x2 %0, %1, %2;" : "=l"(d) : "l"(a), "l"(b))

__device__ __forceinline__ ull pack2(float lo, float hi) {
    ull r; asm("mov.b64 %0, {%1, %2};" : "=l"(r) : "f"(lo), "f"(hi)); return r;
}
__device__ __forceinline__ void unpack2(ull v, float& lo, float& hi) {
    asm("mov.b64 {%0, %1}, %2;" : "=f"(lo), "=f"(hi) : "l"(v));
}

__device__ __forceinline__ void cp_async16(void* smem_dst, const void* gsrc) {
    unsigned s = (unsigned)__cvta_generic_to_shared(smem_dst);
    asm volatile("cp.async.ca.shared.global [%0], [%1], 16;" :: "r"(s), "l"(gsrc));
}
__device__ __forceinline__ void cp_commit() {
    asm volatile("cp.async.commit_group;");
}
__device__ __forceinline__ void cp_wait0() {
    asm volatile("cp.async.wait_group 0;");
}

// Problem constants
constexpr int B  = 8;
constexpr int C  = 256;
constexpr int M  = 64;
constexpr int H  = 128, W = 128, HW = H * W;       // input spatial
constexpr int KK = 25;                              // 5x5 window
constexpr int nH = 64, nW = 64, nHW = nH * nW;      // output spatial

// Scratch (device globals — no allocation allowed)
__device__ float g_mid[(size_t)B * M * HW];    // conv1x1 output (33.5 MB)
__device__ float g_ker[(size_t)B * KK * nHW];  // softmax kernel (3.3 MB)

// ---------------------------------------------------------------------------
// Kernel 1: 1x1 conv  C=256 -> M=64, + bias.  GEMM [64,256] x [256, B*HW].
// Register-blocked: each thread computes 8 m x 4 px; channel-m pairs in
// f32x2 lanes (weights pair naturally; only x needs a 1-mov splat).
// cp.async double-buffered x tiles; weights prefetched through registers.
// Per inner step: 3 LDS.128 + 4 MOV + 16 FMA2 (32 MACs) -> FMA2-bound.
// ---------------------------------------------------------------------------
constexpr int KC = 16;    // channels per chunk
constexpr int PT = 128;   // pixels per block

__global__ void __launch_bounds__(256) k1_conv1x1(
    const float* __restrict__ x, const float* __restrict__ w1,
    const float* __restrict__ b1)
{
    __shared__ float w_s[2][KC][64];   // w_s[buf][cc][m]
    __shared__ float x_s[2][KC][PT];   // x_s[buf][cc][p]

    const int t   = threadIdx.x;
    const int bx  = blockIdx.x;
    const int b   = bx >> 7;
    const int p0  = (bx & 127) * PT;
    const int mg  = t & 7,  pg = t >> 3;
    const int m0  = mg * 8, px0 = pg * 4;

    const float* xb = x + (size_t)b * C * HW + p0;

    // load roles
    const int wm  = t & 63;            // m for weight fill
    const int wc4 = (t >> 6) * 4;      // 4 consecutive cc per thread
    const int xc0 = t >> 5;            // cc for x fill (f = t)
    const int xp0 = (t & 31) * 4;      // p4 for x fill

    ull acc[4][4];
#pragma unroll
    for (int i = 0; i < 4; i++)
#pragma unroll
        for (int p = 0; p < 4; p++) acc[i][p] = 0ULL;

    // ---- prologue: fill buffers for chunk 0 ----
    {
        float4 wq = *(const float4*)&w1[wm * C + 0 + wc4];
        w_s[0][wc4 + 0][wm] = wq.x;
        w_s[0][wc4 + 1][wm] = wq.y;
        w_s[0][wc4 + 2][wm] = wq.z;
        w_s[0][wc4 + 3][wm] = wq.w;
        cp_async16(&x_s[0][xc0][xp0],      xb + (size_t)xc0 * HW + xp0);
        cp_async16(&x_s[0][xc0 + 8][xp0],  xb + (size_t)(xc0 + 8) * HW + xp0);
        cp_commit();
        cp_wait0();
        __syncthreads();
    }

    int cur = 0;
    for (int ch = 0; ch < 16; ch++) {
        const int nxt = cur ^ 1;
        const bool has = (ch < 15);
        float4 wq;
        if (has) {
            const int c0 = (ch + 1) * KC;
            // async prefetch next x tile (latency hidden behind compute)
            cp_async16(&x_s[nxt][xc0][xp0],     xb + (size_t)(c0 + xc0) * HW + xp0);
            cp_async16(&x_s[nxt][xc0 + 8][xp0], xb + (size_t)(c0 + xc0 + 8) * HW + xp0);
            // weight prefetch into registers
            wq = *(const float4*)&w1[wm * C + c0 + wc4];
        }

        // ---- compute 16 channels from current buffers ----
#pragma unroll
        for (int cc = 0; cc < KC; cc++) {
            const float* wr = &w_s[cur][cc][m0];
            ulonglong2 wv0 = *(const ulonglong2*)(wr);       // m-pairs m0..m0+3
            ulonglong2 wv1 = *(const ulonglong2*)(wr + 4);   // m-pairs m0+4..m0+7
            float4 xv = *(const float4*)&x_s[cur][cc][px0];
            ull xs0 = pack2(xv.x, xv.x);
            ull xs1 = pack2(xv.y, xv.y);
            ull xs2 = pack2(xv.z, xv.z);
            ull xs3 = pack2(xv.w, xv.w);
            FMA2(acc[0][0], wv0.x, xs0, acc[0][0]);
            FMA2(acc[0][1], wv0.x, xs1, acc[0][1]);
            FMA2(acc[0][2], wv0.x, xs2, acc[0][2]);
            FMA2(acc[0][3], wv0.x, xs3, acc[0][3]);
            FMA2(acc[1][0], wv0.y, xs0, acc[1][0]);
            FMA2(acc[1][1], wv0.y, xs1, acc[1][1]);
            FMA2(acc[1][2], wv0.y, xs2, acc[1][2]);
            FMA2(acc[1][3], wv0.y, xs3, acc[1][3]);
            FMA2(acc[2][0], wv1.x, xs0, acc[2][0]);
            FMA2(acc[2][1], wv1.x, xs1, acc[2][1]);
            FMA2(acc[2][2], wv1.x, xs2, acc[2][2]);
            FMA2(acc[2][3], wv1.x, xs3, acc[2][3]);
            FMA2(acc[3][0], wv1.y, xs0, acc[3][0]);
            FMA2(acc[3][1], wv1.y, xs1, acc[3][1]);
            FMA2(acc[3][2], wv1.y, xs2, acc[3][2]);
            FMA2(acc[3][3], wv1.y, xs3, acc[3][3]);
        }

        if (has) {
            w_s[nxt][wc4 + 0][wm] = wq.x;
            w_s[nxt][wc4 + 1][wm] = wq.y;
            w_s[nxt][wc4 + 2][wm] = wq.z;
            w_s[nxt][wc4 + 3][wm] = wq.w;
            cp_commit();
        }
        cp_wait0();
        __syncthreads();
        cur = nxt;
    }

    // ---- epilogue: bias + store (float4 per m-row) ----
#pragma unroll
    for (int i = 0; i < 4; i++) {
        ull bp = pack2(b1[m0 + 2 * i], b1[m0 + 2 * i + 1]);
        float lo[4], hi[4];
#pragma unroll
        for (int p = 0; p < 4; p++) {
            ull v; ADD2(v, acc[i][p], bp);
            unpack2(v, lo[p], hi[p]);
        }
        size_t base = ((size_t)(b * M + m0 + 2 * i)) * HW + p0 + px0;
        *(float4*)&g_mid[base]      = make_float4(lo[0], lo[1], lo[2], lo[3]);
        *(float4*)&g_mid[base + HW] = make_float4(hi[0], hi[1], hi[2], hi[3]);
    }
}

// ---------------------------------------------------------------------------
// Kernel 2: 3x3 conv stride 2 pad 1, M=64 -> 25, + bias, + softmax over 25.
// (unchanged from R1 — not the bottleneck)
// ---------------------------------------------------------------------------
__global__ void __launch_bounds__(128) k2_encoder(
    const float* __restrict__ w2, const float* __restrict__ b2)
{
    __shared__ float2 ms[2][17][37];
    __shared__ float2 ws[2][9][26];

    const int t  = threadIdx.x;
    const int b  = blockIdx.z;
    const int h0 = blockIdx.y * 8;
    const int w0 = blockIdx.x * 16;
    const int ty = t >> 4;
    const int tx = t & 15;

    ull acc[25];
#pragma unroll
    for (int k = 0; k < 25; k++) acc[k] = 0ULL;

    for (int chk = 0; chk < 16; chk++) {
        const int c0 = chk * 4;
        for (int idx = t; idx < 450; idx += 128) {
            int cp = idx / 225, r = idx % 225;
            int j = r / 25, k = r % 25;
            int c = c0 + 2 * cp;
            ws[cp][j][k] = make_float2(w2[(k * M + c    ) * 9 + j],
                                       w2[(k * M + c + 1) * 9 + j]);
        }
        for (int idx = t; idx < 2 * 17 * 33; idx += 128) {
            int cp = idx / 561, r = idx % 561;
            int i = r / 33, jj = r % 33;
            int ih = 2 * h0 - 1 + i, iw = 2 * w0 - 1 + jj;
            float v0 = 0.f, v1 = 0.f;
            if ((unsigned)ih < 128u && (unsigned)iw < 128u) {
                size_t base = ((size_t)(b * M + c0 + 2 * cp)) * HW + ih * W + iw;
                v0 = g_mid[base];
                v1 = g_mid[base + HW];
            }
            ms[cp][i][jj] = make_float2(v0, v1);
        }
        __syncthreads();
#pragma unroll
        for (int cp = 0; cp < 2; cp++) {
            ull xp[9];
#pragma unroll
            for (int i = 0; i < 3; i++)
#pragma unroll
                for (int j = 0; j < 3; j++)
                    xp[i * 3 + j] = *(const ull*)&ms[cp][2 * ty + i][2 * tx + j];
#pragma unroll
            for (int j9 = 0; j9 < 9; j9++) {
#pragma unroll
                for (int k2 = 0; k2 < 12; k2++) {
                    ulonglong2 wq = *(const ulonglong2*)&ws[cp][j9][2 * k2];
                    FMA2(acc[2*k2  ], wq.x, xp[j9], acc[2*k2  ]);
                    FMA2(acc[2*k2+1], wq.y, xp[j9], acc[2*k2+1]);
                }
                ull wl = *(const ull*)&ws[cp][j9][24];
                FMA2(acc[24], wl, xp[j9], acc[24]);
            }
        }
        __syncthreads();
    }

    float lg[25];
#pragma unroll
    for (int k = 0; k < 25; k++) {
        float a, bq; unpack2(acc[k], a, bq);
        lg[k] = a + bq + b2[k];
    }
    float mx = lg[0];
#pragma unroll
    for (int k = 1; k < 25; k++) mx = fmaxf(mx, lg[k]);
    float e[25], s = 0.f;
#pragma unroll
    for (int k = 0; k < 25; k++) { e[k] = __expf(lg[k] - mx); s += e[k]; }
    const float inv = 1.f / s;
    const int h = h0 + ty, w = w0 + tx;
    const size_t base = ((size_t)b * KK) * nHW + h * nW + w;
#pragma unroll
    for (int k = 0; k < 25; k++)
        g_ker[base + (size_t)k * nHW] = e[k] * inv;
}

// ---------------------------------------------------------------------------
// Kernel 3: softmax-weighted 5x5 window sum over x (stride 2, pad 2).
// Two channel-pairs per smem stage (half the barriers), 64 channels/block
// (2x more blocks than R1 for wave coverage).
// ---------------------------------------------------------------------------
__global__ void __launch_bounds__(256) k3_apply(
    const float* __restrict__ x, float* __restrict__ out)
{
    __shared__ float2 xi[2][35][38];   // [cpair][row][col], padded row

    const int t  = threadIdx.x;
    const int bz = blockIdx.z;
    const int b  = bz >> 2;
    const int cbase = (bz & 3) * 64;
    const int h0 = blockIdx.y * 16, w0 = blockIdx.x * 16;
    const int py = t >> 4, px = t & 15;
    const int h = h0 + py, w = w0 + px;

    ull kp[25];
#pragma unroll
    for (int k = 0; k < 25; k++) {
        float kv = g_ker[((size_t)(b * KK + k)) * nHW + h * nW + w];
        kp[k] = pack2(kv, kv);
    }

    const int ir0 = 2 * h0 - 2, ic0 = 2 * w0 - 2;

    for (int c = cbase; c < cbase + 64; c += 4) {
        __syncthreads();
        const float* xc0 = x + ((size_t)(b * C + c)) * HW;
        for (int idx = t; idx < 2 * 35 * 35; idx += 256) {
            int cp = (idx >= 1225) ? 1 : 0;
            int rr = idx - cp * 1225;
            int r = rr / 35, cc = rr - r * 35;
            int ir = ir0 + r, ic = ic0 + cc;
            float v0 = 0.f, v1 = 0.f;
            if ((unsigned)ir < 128u && (unsigned)ic < 128u) {
                size_t base = (size_t)(2 * cp) * HW + ir * W + ic;
                v0 = xc0[base];
                v1 = xc0[base + HW];
            }
            xi[cp][r][cc] = make_float2(v0, v1);
        }
        __syncthreads();

#pragma unroll
        for (int cp = 0; cp < 2; cp++) {
            ull a[5];
#pragma unroll
            for (int i = 0; i < 5; i++) a[i] = 0ULL;
#pragma unroll
            for (int i = 0; i < 5; i++)
#pragma unroll
                for (int j = 0; j < 5; j++) {
                    ull xv = *(const ull*)&xi[cp][2 * py + i][2 * px + j];
                    const int k = i * 5 + j;
                    FMA2(a[k % 5], kp[k], xv, a[k % 5]);
                }
            ull s01, s23, s;
            ADD2(s01, a[0], a[1]);
            ADD2(s23, a[2], a[3]);
            ADD2(s01, s01, s23);
            ADD2(s, s01, a[4]);
            float o0, o1; unpack2(s, o0, o1);
            const size_t obase = ((size_t)(b * C + c + 2 * cp)) * nHW + h * nW + w;
            out[obase]       = o0;
            out[obase + nHW] = o1;
        }
    }
}

// ---------------------------------------------------------------------------
extern "C" void kernel_launch(void* const* d_in, const int* in_sizes, int n_in,
                              void* d_out, int out_size)
{
    (void)in_sizes; (void)n_in; (void)out_size;
    const float* x  = (const float*)d_in[0];
    const float* w1 = (const float*)d_in[1];
    const float* b1 = (const float*)d_in[2];
    const float* w2 = (const float*)d_in[3];
    const float* b2 = (const float*)d_in[4];
    float* out = (float*)d_out;

    k1_conv1x1<<<1024, 256>>>(x, w1, b1);                // mid = conv1x1(x)+b1
    k2_encoder<<<dim3(4, 8, 8), 128>>>(w2, b2);          // ker = softmax(conv3x3(mid)+b2)
    k3_apply<<<dim3(4, 4, 32), 256>>>(x, out);           // out = weighted window sum
}

// round 6
// speedup vs baseline: 2.9761x; 2.0092x over previous
#include <cuda_runtime.h>
#include <cstdint>

typedef unsigned long long ull;

// Packed fp32x2 FMA (sm_100+/sm_103a; ptxas never auto-generates this)
#define FMA2(d, a, b, c) \
    asm("fma.rn.f32x2 %0, %1, %2, %3;" : "=l"(d) : "l"(a), "l"(b), "l"(c))
#define ADD2(d, a, b) \
    asm("add.rn.f32x2 %0, %1, %2;" : "=l"(d) : "l"(a), "l"(b))

__device__ __forceinline__ ull pack2(float lo, float hi) {
    ull r; asm("mov.b64 %0, {%1, %2};" : "=l"(r) : "f"(lo), "f"(hi)); return r;
}
__device__ __forceinline__ void unpack2(ull v, float& lo, float& hi) {
    asm("mov.b64 {%0, %1}, %2;" : "=f"(lo), "=f"(hi) : "l"(v));
}

__device__ __forceinline__ void cp_async16cg(void* smem_dst, const void* gsrc) {
    unsigned s = (unsigned)__cvta_generic_to_shared(smem_dst);
    asm volatile("cp.async.cg.shared.global [%0], [%1], 16;" :: "r"(s), "l"(gsrc));
}
#define CP_COMMIT()  asm volatile("cp.async.commit_group;")
#define CP_WAIT(n)   asm volatile("cp.async.wait_group %0;" :: "n"(n))

// Problem constants
constexpr int B  = 8;
constexpr int C  = 256;
constexpr int M  = 64;
constexpr int H  = 128, W = 128, HW = H * W;       // input spatial
constexpr int KK = 25;                              // 5x5 window
constexpr int nH = 64, nW = 64, nHW = nH * nW;      // output spatial

// Scratch (device globals — no allocation allowed)
__device__ float g_mid[(size_t)B * M * HW];    // conv1x1 output (33.5 MB)
__device__ float g_ker[(size_t)B * KK * nHW];  // softmax kernel (3.3 MB)

// ---------------------------------------------------------------------------
// Kernel 1: 1x1 conv  C=256 -> M=64 + bias.  GEMM [64,256] x [256, B*HW].
// 256 threads, tile = 256 px x 64 m.  Thread tile: 8 m (4 m-pairs in f32x2
// lanes) x 8 px.  Per cc-step: 2 broadcast LDS.128 (w) + 2 swizzled LDS.128
// (x) + 8 splat movs + 32 FMA2 (64 MACs) -> FMA2-pipe bound.
// Weights staged once (64KB smem); x double-buffered via cp.async.cg with a
// real 1-group-in-flight pipeline.
// ---------------------------------------------------------------------------
constexpr int PT1 = 256;    // pixels per block
constexpr int KC1 = 16;     // channels per chunk
constexpr int SM1_W = 0;                    // w_s[c][m]: 256*64*4   = 65536
constexpr int SM1_X = 65536;                // x_s[2][16][256 floats] = 32768
constexpr int SM1_TOTAL = 65536 + 32768;    // 98304

__device__ __forceinline__ uint32_t sw128(uint32_t o) {
    return o ^ ((o >> 3) & 0x70u);
}

__global__ void __launch_bounds__(256, 2) k1_conv1x1(
    const float* __restrict__ x, const float* __restrict__ w1,
    const float* __restrict__ b1)
{
    extern __shared__ char smem[];
    float* w_s = (float*)(smem + SM1_W);
    char*  x_s = smem + SM1_X;

    const int t    = threadIdx.x;
    const int bx   = blockIdx.x;          // 512 blocks
    const int b    = bx >> 6;
    const int p0   = (bx & 63) * PT1;
    const int warp = t >> 5, lane = t & 31;
    const int m0   = warp * 8;
    const int px0  = lane * 8;

    const float* xb = x + (size_t)(b * C) * HW + p0;

    // x-fill roles: cc = t>>4 (16 channels), 4 float4s per thread per chunk
    const int xcc = t >> 4;
    const int xc4 = t & 15;
    // precomputed swizzled dst offsets within a 1KB row
    uint32_t dsw[4];
#pragma unroll
    for (int j = 0; j < 4; j++) dsw[j] = sw128((uint32_t)((xc4 + j * 16) * 16));

    // compute-side swizzled x offsets (within row)
    const uint32_t s1 = sw128((uint32_t)(lane * 32));
    const uint32_t s2 = sw128((uint32_t)(lane * 32 + 16));

    // ---- issue chunk 0 and 1 prefetches FIRST (overlap w-staging) ----
#pragma unroll
    for (int j = 0; j < 4; j++)
        cp_async16cg(x_s + xcc * 1024 + dsw[j],
                     xb + (size_t)xcc * HW + xc4 * 4 + j * 64);
    CP_COMMIT();
#pragma unroll
    for (int j = 0; j < 4; j++)
        cp_async16cg(x_s + 16384 + xcc * 1024 + dsw[j],
                     xb + (size_t)(KC1 + xcc) * HW + xc4 * 4 + j * 64);
    CP_COMMIT();

    // ---- stage weights once: w_s[c][m], conflict-free transpose ----
#pragma unroll
    for (int it = 0; it < 16; it++) {
        int gid = it * 256 + t;
        int m  = gid & 63;
        int c4 = (gid >> 6) * 4;
        float4 wq = *(const float4*)&w1[m * C + c4];
        w_s[(c4 + 0) * 64 + m] = wq.x;
        w_s[(c4 + 1) * 64 + m] = wq.y;
        w_s[(c4 + 2) * 64 + m] = wq.z;
        w_s[(c4 + 3) * 64 + m] = wq.w;
    }

    ull acc[4][8];
#pragma unroll
    for (int i = 0; i < 4; i++)
#pragma unroll
        for (int p = 0; p < 8; p++) acc[i][p] = 0ULL;

    CP_WAIT(1);
    __syncthreads();

    int cur = 0;
#pragma unroll 1
    for (int ch = 0; ch < 16; ch++) {
        const char* xrow = x_s + cur * 16384;
        const float* wc  = w_s + (ch * KC1) * 64 + m0;
#pragma unroll
        for (int cc = 0; cc < KC1; cc++) {
            ulonglong2 wv0 = *(const ulonglong2*)(wc + cc * 64);      // m-pairs 0,1
            ulonglong2 wv1 = *(const ulonglong2*)(wc + cc * 64 + 4);  // m-pairs 2,3
            float4 xa = *(const float4*)(xrow + cc * 1024 + s1);
            float4 xc = *(const float4*)(xrow + cc * 1024 + s2);
            ull xs[8];
            xs[0] = pack2(xa.x, xa.x); xs[1] = pack2(xa.y, xa.y);
            xs[2] = pack2(xa.z, xa.z); xs[3] = pack2(xa.w, xa.w);
            xs[4] = pack2(xc.x, xc.x); xs[5] = pack2(xc.y, xc.y);
            xs[6] = pack2(xc.z, xc.z); xs[7] = pack2(xc.w, xc.w);
#pragma unroll
            for (int p = 0; p < 8; p++) {
                FMA2(acc[0][p], wv0.x, xs[p], acc[0][p]);
                FMA2(acc[1][p], wv0.y, xs[p], acc[1][p]);
                FMA2(acc[2][p], wv1.x, xs[p], acc[2][p]);
                FMA2(acc[3][p], wv1.y, xs[p], acc[3][p]);
            }
        }
        __syncthreads();
        if (ch < 14) {
            const int cnext = (ch + 2) * KC1;
#pragma unroll
            for (int j = 0; j < 4; j++)
                cp_async16cg(x_s + cur * 16384 + xcc * 1024 + dsw[j],
                             xb + (size_t)(cnext + xcc) * HW + xc4 * 4 + j * 64);
            CP_COMMIT();
            CP_WAIT(1);
        } else {
            CP_WAIT(0);
        }
        __syncthreads();
        cur ^= 1;
    }

    // ---- epilogue: bias + store ----
#pragma unroll
    for (int i = 0; i < 4; i++) {
        ull bp = pack2(b1[m0 + 2 * i], b1[m0 + 2 * i + 1]);
        float lo[8], hi[8];
#pragma unroll
        for (int p = 0; p < 8; p++) {
            ull v; ADD2(v, acc[i][p], bp);
            unpack2(v, lo[p], hi[p]);
        }
        size_t base = ((size_t)(b * M + m0 + 2 * i)) * HW + p0 + px0;
        *(float4*)&g_mid[base]          = make_float4(lo[0], lo[1], lo[2], lo[3]);
        *(float4*)&g_mid[base + 4]      = make_float4(lo[4], lo[5], lo[6], lo[7]);
        *(float4*)&g_mid[base + HW]     = make_float4(hi[0], hi[1], hi[2], hi[3]);
        *(float4*)&g_mid[base + HW + 4] = make_float4(hi[4], hi[5], hi[6], hi[7]);
    }
}

// ---------------------------------------------------------------------------
// Kernel 2: 3x3 conv stride 2 pad 1, M=64 -> 25, + bias, + softmax over 25.
// ---------------------------------------------------------------------------
__global__ void __launch_bounds__(128) k2_encoder(
    const float* __restrict__ w2, const float* __restrict__ b2)
{
    __shared__ float2 ms[2][17][37];
    __shared__ float2 ws[2][9][26];

    const int t  = threadIdx.x;
    const int b  = blockIdx.z;
    const int h0 = blockIdx.y * 8;
    const int w0 = blockIdx.x * 16;
    const int ty = t >> 4;
    const int tx = t & 15;

    ull acc[25];
#pragma unroll
    for (int k = 0; k < 25; k++) acc[k] = 0ULL;

    for (int chk = 0; chk < 16; chk++) {
        const int c0 = chk * 4;
        for (int idx = t; idx < 450; idx += 128) {
            int cp = idx / 225, r = idx % 225;
            int j = r / 25, k = r % 25;
            int c = c0 + 2 * cp;
            ws[cp][j][k] = make_float2(w2[(k * M + c    ) * 9 + j],
                                       w2[(k * M + c + 1) * 9 + j]);
        }
        for (int idx = t; idx < 2 * 17 * 33; idx += 128) {
            int cp = idx / 561, r = idx % 561;
            int i = r / 33, jj = r % 33;
            int ih = 2 * h0 - 1 + i, iw = 2 * w0 - 1 + jj;
            float v0 = 0.f, v1 = 0.f;
            if ((unsigned)ih < 128u && (unsigned)iw < 128u) {
                size_t base = ((size_t)(b * M + c0 + 2 * cp)) * HW + ih * W + iw;
                v0 = g_mid[base];
                v1 = g_mid[base + HW];
            }
            ms[cp][i][jj] = make_float2(v0, v1);
        }
        __syncthreads();
#pragma unroll
        for (int cp = 0; cp < 2; cp++) {
            ull xp[9];
#pragma unroll
            for (int i = 0; i < 3; i++)
#pragma unroll
                for (int j = 0; j < 3; j++)
                    xp[i * 3 + j] = *(const ull*)&ms[cp][2 * ty + i][2 * tx + j];
#pragma unroll
            for (int j9 = 0; j9 < 9; j9++) {
#pragma unroll
                for (int k2 = 0; k2 < 12; k2++) {
                    ulonglong2 wq = *(const ulonglong2*)&ws[cp][j9][2 * k2];
                    FMA2(acc[2*k2  ], wq.x, xp[j9], acc[2*k2  ]);
                    FMA2(acc[2*k2+1], wq.y, xp[j9], acc[2*k2+1]);
                }
                ull wl = *(const ull*)&ws[cp][j9][24];
                FMA2(acc[24], wl, xp[j9], acc[24]);
            }
        }
        __syncthreads();
    }

    float lg[25];
#pragma unroll
    for (int k = 0; k < 25; k++) {
        float a, bq; unpack2(acc[k], a, bq);
        lg[k] = a + bq + b2[k];
    }
    float mx = lg[0];
#pragma unroll
    for (int k = 1; k < 25; k++) mx = fmaxf(mx, lg[k]);
    float e[25], s = 0.f;
#pragma unroll
    for (int k = 0; k < 25; k++) { e[k] = __expf(lg[k] - mx); s += e[k]; }
    const float inv = 1.f / s;
    const int h = h0 + ty, w = w0 + tx;
    const size_t base = ((size_t)b * KK) * nHW + h * nW + w;
#pragma unroll
    for (int k = 0; k < 25; k++)
        g_ker[base + (size_t)k * nHW] = e[k] * inv;
}

// ---------------------------------------------------------------------------
// Kernel 3: softmax-weighted 5x5 window sum over x (stride 2, pad 2).
// ---------------------------------------------------------------------------
__global__ void __launch_bounds__(256) k3_apply(
    const float* __restrict__ x, float* __restrict__ out)
{
    __shared__ float2 xi[2][35][38];

    const int t  = threadIdx.x;
    const int bz = blockIdx.z;
    const int b  = bz >> 2;
    const int cbase = (bz & 3) * 64;
    const int h0 = blockIdx.y * 16, w0 = blockIdx.x * 16;
    const int py = t >> 4, px = t & 15;
    const int h = h0 + py, w = w0 + px;

    ull kp[25];
#pragma unroll
    for (int k = 0; k < 25; k++) {
        float kv = g_ker[((size_t)(b * KK + k)) * nHW + h * nW + w];
        kp[k] = pack2(kv, kv);
    }

    const int ir0 = 2 * h0 - 2, ic0 = 2 * w0 - 2;

    for (int c = cbase; c < cbase + 64; c += 4) {
        __syncthreads();
        const float* xc0 = x + ((size_t)(b * C + c)) * HW;
        for (int idx = t; idx < 2 * 35 * 35; idx += 256) {
            int cp = (idx >= 1225) ? 1 : 0;
            int rr = idx - cp * 1225;
            int r = rr / 35, cc = rr - r * 35;
            int ir = ir0 + r, ic = ic0 + cc;
            float v0 = 0.f, v1 = 0.f;
            if ((unsigned)ir < 128u && (unsigned)ic < 128u) {
                size_t base = (size_t)(2 * cp) * HW + ir * W + ic;
                v0 = xc0[base];
                v1 = xc0[base + HW];
            }
            xi[cp][r][cc] = make_float2(v0, v1);
        }
        __syncthreads();

#pragma unroll
        for (int cp = 0; cp < 2; cp++) {
            ull a[5];
#pragma unroll
            for (int i = 0; i < 5; i++) a[i] = 0ULL;
#pragma unroll
            for (int i = 0; i < 5; i++)
#pragma unroll
                for (int j = 0; j < 5; j++) {
                    ull xv = *(const ull*)&xi[cp][2 * py + i][2 * px + j];
                    const int k = i * 5 + j;
                    FMA2(a[k % 5], kp[k], xv, a[k % 5]);
                }
            ull s01, s23, s;
            ADD2(s01, a[0], a[1]);
            ADD2(s23, a[2], a[3]);
            ADD2(s01, s01, s23);
            ADD2(s, s01, a[4]);
            float o0, o1; unpack2(s, o0, o1);
            const size_t obase = ((size_t)(b * C + c + 2 * cp)) * nHW + h * nW + w;
            out[obase]       = o0;
            out[obase + nHW] = o1;
        }
    }
}

// ---------------------------------------------------------------------------
extern "C" void kernel_launch(void* const* d_in, const int* in_sizes, int n_in,
                              void* d_out, int out_size)
{
    (void)in_sizes; (void)n_in; (void)out_size;
    const float* x  = (const float*)d_in[0];
    const float* w1 = (const float*)d_in[1];
    const float* b1 = (const float*)d_in[2];
    const float* w2 = (const float*)d_in[3];
    const float* b2 = (const float*)d_in[4];
    float* out = (float*)d_out;

    cudaFuncSetAttribute(k1_conv1x1,
                         cudaFuncAttributeMaxDynamicSharedMemorySize, SM1_TOTAL);
    k1_conv1x1<<<512, 256, SM1_TOTAL>>>(x, w1, b1);
    k2_encoder<<<dim3(4, 8, 8), 128>>>(w2, b2);
    k3_apply<<<dim3(4, 4, 32), 256>>>(x, out);
}

// round 8
// speedup vs baseline: 4.2660x; 1.4334x over previous
#include <cuda_runtime.h>
#include <cstdint>

typedef unsigned long long ull;

// Packed fp32x2 FMA (sm_100+/sm_103a; ptxas never auto-generates this)
#define FMA2(d, a, b, c) \
    asm("fma.rn.f32x2 %0, %1, %2, %3;" : "=l"(d) : "l"(a), "l"(b), "l"(c))
#define ADD2(d, a, b) \
    asm("add.rn.f32x2 %0, %1, %2;" : "=l"(d) : "l"(a), "l"(b))

__device__ __forceinline__ ull pack2(float lo, float hi) {
    ull r; asm("mov.b64 %0, {%1, %2};" : "=l"(r) : "f"(lo), "f"(hi)); return r;
}
__device__ __forceinline__ void unpack2(ull v, float& lo, float& hi) {
    asm("mov.b64 {%0, %1}, %2;" : "=f"(lo), "=f"(hi) : "l"(v));
}

__device__ __forceinline__ void cp_async16cg(void* smem_dst, const void* gsrc) {
    unsigned s = (unsigned)__cvta_generic_to_shared(smem_dst);
    asm volatile("cp.async.cg.shared.global [%0], [%1], 16;" :: "r"(s), "l"(gsrc));
}
#define CP_COMMIT()  asm volatile("cp.async.commit_group;")
#define CP_WAIT(n)   asm volatile("cp.async.wait_group %0;" :: "n"(n))

// Problem constants
constexpr int B  = 8;
constexpr int C  = 256;
constexpr int M  = 64;
constexpr int H  = 128, W = 128, HW = H * W;       // input spatial
constexpr int KK = 25;                              // 5x5 window
constexpr int nH = 64, nW = 64, nHW = nH * nW;      // output spatial

// Scratch (device globals — no allocation allowed)
__device__ float g_mid[(size_t)B * M * HW];    // conv1x1 output (33.5 MB)
__device__ float g_ker[(size_t)B * KK * nHW];  // softmax kernel (3.3 MB)

// ---------------------------------------------------------------------------
// Kernel 1: 1x1 conv (UNCHANGED from R5 — 98.5us, fma 54.6%)
// ---------------------------------------------------------------------------
constexpr int PT1 = 256;    // pixels per block
constexpr int KC1 = 16;     // channels per chunk
constexpr int SM1_W = 0;                    // w_s[c][m]: 256*64*4   = 65536
constexpr int SM1_X = 65536;                // x_s[2][16][256 floats] = 32768
constexpr int SM1_TOTAL = 65536 + 32768;    // 98304

__device__ __forceinline__ uint32_t sw128(uint32_t o) {
    return o ^ ((o >> 3) & 0x70u);
}

__global__ void __launch_bounds__(256, 2) k1_conv1x1(
    const float* __restrict__ x, const float* __restrict__ w1,
    const float* __restrict__ b1)
{
    extern __shared__ char smem[];
    float* w_s = (float*)(smem + SM1_W);
    char*  x_s = smem + SM1_X;

    const int t    = threadIdx.x;
    const int bx   = blockIdx.x;          // 512 blocks
    const int b    = bx >> 6;
    const int p0   = (bx & 63) * PT1;
    const int warp = t >> 5, lane = t & 31;
    const int m0   = warp * 8;
    const int px0  = lane * 8;

    const float* xb = x + (size_t)(b * C) * HW + p0;

    const int xcc = t >> 4;
    const int xc4 = t & 15;
    uint32_t dsw[4];
#pragma unroll
    for (int j = 0; j < 4; j++) dsw[j] = sw128((uint32_t)((xc4 + j * 16) * 16));

    const uint32_t s1 = sw128((uint32_t)(lane * 32));
    const uint32_t s2 = sw128((uint32_t)(lane * 32 + 16));

#pragma unroll
    for (int j = 0; j < 4; j++)
        cp_async16cg(x_s + xcc * 1024 + dsw[j],
                     xb + (size_t)xcc * HW + xc4 * 4 + j * 64);
    CP_COMMIT();
#pragma unroll
    for (int j = 0; j < 4; j++)
        cp_async16cg(x_s + 16384 + xcc * 1024 + dsw[j],
                     xb + (size_t)(KC1 + xcc) * HW + xc4 * 4 + j * 64);
    CP_COMMIT();

#pragma unroll
    for (int it = 0; it < 16; it++) {
        int gid = it * 256 + t;
        int m  = gid & 63;
        int c4 = (gid >> 6) * 4;
        float4 wq = *(const float4*)&w1[m * C + c4];
        w_s[(c4 + 0) * 64 + m] = wq.x;
        w_s[(c4 + 1) * 64 + m] = wq.y;
        w_s[(c4 + 2) * 64 + m] = wq.z;
        w_s[(c4 + 3) * 64 + m] = wq.w;
    }

    ull acc[4][8];
#pragma unroll
    for (int i = 0; i < 4; i++)
#pragma unroll
        for (int p = 0; p < 8; p++) acc[i][p] = 0ULL;

    CP_WAIT(1);
    __syncthreads();

    int cur = 0;
#pragma unroll 1
    for (int ch = 0; ch < 16; ch++) {
        const char* xrow = x_s + cur * 16384;
        const float* wc  = w_s + (ch * KC1) * 64 + m0;
#pragma unroll
        for (int cc = 0; cc < KC1; cc++) {
            ulonglong2 wv0 = *(const ulonglong2*)(wc + cc * 64);
            ulonglong2 wv1 = *(const ulonglong2*)(wc + cc * 64 + 4);
            float4 xa = *(const float4*)(xrow + cc * 1024 + s1);
            float4 xc = *(const float4*)(xrow + cc * 1024 + s2);
            ull xs[8];
            xs[0] = pack2(xa.x, xa.x); xs[1] = pack2(xa.y, xa.y);
            xs[2] = pack2(xa.z, xa.z); xs[3] = pack2(xa.w, xa.w);
            xs[4] = pack2(xc.x, xc.x); xs[5] = pack2(xc.y, xc.y);
            xs[6] = pack2(xc.z, xc.z); xs[7] = pack2(xc.w, xc.w);
#pragma unroll
            for (int p = 0; p < 8; p++) {
                FMA2(acc[0][p], wv0.x, xs[p], acc[0][p]);
                FMA2(acc[1][p], wv0.y, xs[p], acc[1][p]);
                FMA2(acc[2][p], wv1.x, xs[p], acc[2][p]);
                FMA2(acc[3][p], wv1.y, xs[p], acc[3][p]);
            }
        }
        __syncthreads();
        if (ch < 14) {
            const int cnext = (ch + 2) * KC1;
#pragma unroll
            for (int j = 0; j < 4; j++)
                cp_async16cg(x_s + cur * 16384 + xcc * 1024 + dsw[j],
                             xb + (size_t)(cnext + xcc) * HW + xc4 * 4 + j * 64);
            CP_COMMIT();
            CP_WAIT(1);
        } else {
            CP_WAIT(0);
        }
        __syncthreads();
        cur ^= 1;
    }

#pragma unroll
    for (int i = 0; i < 4; i++) {
        ull bp = pack2(b1[m0 + 2 * i], b1[m0 + 2 * i + 1]);
        float lo[8], hi[8];
#pragma unroll
        for (int p = 0; p < 8; p++) {
            ull v; ADD2(v, acc[i][p], bp);
            unpack2(v, lo[p], hi[p]);
        }
        size_t base = ((size_t)(b * M + m0 + 2 * i)) * HW + p0 + px0;
        *(float4*)&g_mid[base]          = make_float4(lo[0], lo[1], lo[2], lo[3]);
        *(float4*)&g_mid[base + 4]      = make_float4(lo[4], lo[5], lo[6], lo[7]);
        *(float4*)&g_mid[base + HW]     = make_float4(hi[0], hi[1], hi[2], hi[3]);
        *(float4*)&g_mid[base + HW + 4] = make_float4(hi[4], hi[5], hi[6], hi[7]);
    }
}

// ---------------------------------------------------------------------------
// Kernel 2: 3x3 conv s2 p1, 64->25, + bias + softmax.  Pipelined: fill slots
// precomputed once (iteration-invariant addressing), register prefetch of
// chunk i+1 during compute of chunk i, ONE sync per chunk.
// ---------------------------------------------------------------------------
__global__ void __launch_bounds__(128) k2_encoder(
    const float* __restrict__ w2, const float* __restrict__ b2)
{
    __shared__ float2 ms[2][2][17][37];   // [buf][cpair][row][col]
    __shared__ float2 ws[2][2][9][26];    // [buf][cpair][j][k]

    const int t  = threadIdx.x;
    const int b  = blockIdx.z;
    const int h0 = blockIdx.y * 8;
    const int w0 = blockIdx.x * 16;
    const int ty = t >> 4;
    const int tx = t & 15;

    constexpr int MS_BUF = 2 * 17 * 37;   // float2 stride between buffers
    constexpr int WS_BUF = 2 * 9 * 26;
    float2* msb = &ms[0][0][0][0];
    float2* wsb = &ws[0][0][0][0];

    // ---- precompute fill slots (iteration-invariant) ----
    int ms_off[9], ms_di[9];
#pragma unroll
    for (int s = 0; s < 9; s++) {
        int idx = t + s * 128;
        ms_off[s] = -1; ms_di[s] = -1;
        if (idx < 1122) {
            int cp = idx / 561, r = idx % 561;
            int i = r / 33, jj = r % 33;
            int ih = 2 * h0 - 1 + i, iw = 2 * w0 - 1 + jj;
            ms_di[s] = (cp * 17 + i) * 37 + jj;
            if ((unsigned)ih < 128u && (unsigned)iw < 128u)
                ms_off[s] = (b * M + 2 * cp) * HW + ih * W + iw;
        }
    }
    int ws_src[4], ws_di[4];
#pragma unroll
    for (int s = 0; s < 4; s++) {
        int idx = t + s * 128;
        ws_src[s] = -1; ws_di[s] = -1;
        if (idx < 450) {
            int cp = idx / 225, r = idx % 225;
            int j = r / 25, k = r % 25;
            ws_src[s] = (k * M + 2 * cp) * 9 + j;
            ws_di[s] = (cp * 9 + j) * 26 + k;
        }
    }

    float2 mv[9], wvv[4];
    // ---- prologue: fetch + stage chunk 0 ----
#pragma unroll
    for (int s = 0; s < 9; s++) {
        mv[s] = make_float2(0.f, 0.f);
        if (ms_off[s] >= 0) {
            mv[s].x = g_mid[ms_off[s]];
            mv[s].y = g_mid[ms_off[s] + HW];
        }
    }
#pragma unroll
    for (int s = 0; s < 4; s++)
        if (ws_src[s] >= 0)
            wvv[s] = make_float2(w2[ws_src[s]], w2[ws_src[s] + 9]);
#pragma unroll
    for (int s = 0; s < 9; s++) if (ms_di[s] >= 0) msb[ms_di[s]] = mv[s];
#pragma unroll
    for (int s = 0; s < 4; s++) if (ws_di[s] >= 0) wsb[ws_di[s]] = wvv[s];
    __syncthreads();

    ull acc[25];
#pragma unroll
    for (int k = 0; k < 25; k++) acc[k] = 0ULL;

    int cur = 0;
#pragma unroll 1
    for (int chk = 0; chk < 16; chk++) {
        // prefetch chunk chk+1 into registers
        if (chk < 15) {
            const int moff = (chk + 1) * 4 * HW;
#pragma unroll
            for (int s = 0; s < 9; s++) {
                mv[s] = make_float2(0.f, 0.f);
                if (ms_off[s] >= 0) {
                    mv[s].x = g_mid[ms_off[s] + moff];
                    mv[s].y = g_mid[ms_off[s] + moff + HW];
                }
            }
            const int woff = (chk + 1) * 36;
#pragma unroll
            for (int s = 0; s < 4; s++)
                if (ws_src[s] >= 0)
                    wvv[s] = make_float2(w2[ws_src[s] + woff],
                                         w2[ws_src[s] + woff + 9]);
        }

        // compute from buffer cur
#pragma unroll
        for (int cp = 0; cp < 2; cp++) {
            ull xp[9];
#pragma unroll
            for (int i = 0; i < 3; i++)
#pragma unroll
                for (int j = 0; j < 3; j++)
                    xp[i * 3 + j] = *(const ull*)&ms[cur][cp][2 * ty + i][2 * tx + j];
#pragma unroll
            for (int j9 = 0; j9 < 9; j9++) {
#pragma unroll
                for (int k2 = 0; k2 < 12; k2++) {
                    ulonglong2 wq = *(const ulonglong2*)&ws[cur][cp][j9][2 * k2];
                    FMA2(acc[2*k2  ], wq.x, xp[j9], acc[2*k2  ]);
                    FMA2(acc[2*k2+1], wq.y, xp[j9], acc[2*k2+1]);
                }
                ull wl = *(const ull*)&ws[cur][cp][j9][24];
                FMA2(acc[24], wl, xp[j9], acc[24]);
            }
        }

        // stage chunk chk+1 into the other buffer, single sync
        if (chk < 15) {
            const int nb = cur ^ 1;
#pragma unroll
            for (int s = 0; s < 9; s++)
                if (ms_di[s] >= 0) msb[nb * MS_BUF + ms_di[s]] = mv[s];
#pragma unroll
            for (int s = 0; s < 4; s++)
                if (ws_di[s] >= 0) wsb[nb * WS_BUF + ws_di[s]] = wvv[s];
            __syncthreads();
        }
        cur ^= 1;
    }

    float lg[25];
#pragma unroll
    for (int k = 0; k < 25; k++) {
        float a, bq; unpack2(acc[k], a, bq);
        lg[k] = a + bq + b2[k];
    }
    float mx = lg[0];
#pragma unroll
    for (int k = 1; k < 25; k++) mx = fmaxf(mx, lg[k]);
    float e[25], sum = 0.f;
#pragma unroll
    for (int k = 0; k < 25; k++) { e[k] = __expf(lg[k] - mx); sum += e[k]; }
    const float inv = 1.f / sum;
    const int h = h0 + ty, w = w0 + tx;
    const size_t base = ((size_t)b * KK) * nHW + h * nW + w;
#pragma unroll
    for (int k = 0; k < 25; k++)
        g_ker[base + (size_t)k * nHW] = e[k] * inv;
}

// ---------------------------------------------------------------------------
// Kernel 3: softmax-weighted 5x5 window sum.  Same pipelining scheme:
// precomputed slots, register prefetch, one sync per 4-channel stage.
// ---------------------------------------------------------------------------
__global__ void __launch_bounds__(256) k3_apply(
    const float* __restrict__ x, float* __restrict__ out)
{
    __shared__ float2 xi[2][2][35][38];   // [buf][cpair][row][col]

    const int t  = threadIdx.x;
    const int bz = blockIdx.z;
    const int b  = bz >> 2;
    const int cbase = (bz & 3) * 64;
    const int h0 = blockIdx.y * 16, w0 = blockIdx.x * 16;
    const int py = t >> 4, px = t & 15;
    const int h = h0 + py, w = w0 + px;

    constexpr int XI_BUF = 2 * 35 * 38;
    float2* xib = &xi[0][0][0][0];

    ull kp[25];
#pragma unroll
    for (int k = 0; k < 25; k++) {
        float kv = g_ker[((size_t)(b * KK + k)) * nHW + h * nW + w];
        kp[k] = pack2(kv, kv);
    }

    const int ir0 = 2 * h0 - 2, ic0 = 2 * w0 - 2;
    const float* xb = x + ((size_t)(b * C + cbase)) * HW;

    // ---- precompute fill slots ----
    int xoff[10], xdi[10];
#pragma unroll
    for (int s = 0; s < 10; s++) {
        int idx = t + s * 256;
        xoff[s] = -1; xdi[s] = -1;
        if (idx < 2450) {
            int cp = (idx >= 1225) ? 1 : 0;
            int rr = idx - cp * 1225;
            int r = rr / 35, cc = rr - r * 35;
            int ir = ir0 + r, ic = ic0 + cc;
            xdi[s] = (cp * 35 + r) * 38 + cc;
            if ((unsigned)ir < 128u && (unsigned)ic < 128u)
                xoff[s] = cp * 2 * HW + ir * W + ic;
        }
    }

    float2 xv[10];
    // ---- prologue: stage c-iter 0 ----
#pragma unroll
    for (int s = 0; s < 10; s++) {
        xv[s] = make_float2(0.f, 0.f);
        if (xoff[s] >= 0) {
            xv[s].x = xb[xoff[s]];
            xv[s].y = xb[xoff[s] + HW];
        }
    }
#pragma unroll
    for (int s = 0; s < 10; s++) if (xdi[s] >= 0) xib[xdi[s]] = xv[s];
    __syncthreads();

    int cur = 0;
#pragma unroll 1
    for (int it = 0; it < 16; it++) {
        if (it < 15) {
            const int coff = (it + 1) * 4 * HW;
#pragma unroll
            for (int s = 0; s < 10; s++) {
                xv[s] = make_float2(0.f, 0.f);
                if (xoff[s] >= 0) {
                    xv[s].x = xb[xoff[s] + coff];
                    xv[s].y = xb[xoff[s] + coff + HW];
                }
            }
        }

        const int c = cbase + it * 4;
#pragma unroll
        for (int cp = 0; cp < 2; cp++) {
            ull a[5];
#pragma unroll
            for (int i = 0; i < 5; i++) a[i] = 0ULL;
#pragma unroll
            for (int i = 0; i < 5; i++)
#pragma unroll
                for (int j = 0; j < 5; j++) {
                    ull xvv = *(const ull*)&xi[cur][cp][2 * py + i][2 * px + j];
                    const int k = i * 5 + j;
                    FMA2(a[k % 5], kp[k], xvv, a[k % 5]);
                }
            ull s01, s23, ssum;
            ADD2(s01, a[0], a[1]);
            ADD2(s23, a[2], a[3]);
            ADD2(s01, s01, s23);
            ADD2(ssum, s01, a[4]);
            float o0, o1; unpack2(ssum, o0, o1);
            const size_t obase = ((size_t)(b * C + c + 2 * cp)) * nHW + h * nW + w;
            out[obase]       = o0;
            out[obase + nHW] = o1;
        }

        if (it < 15) {
            const int nb = cur ^ 1;
#pragma unroll
            for (int s = 0; s < 10; s++)
                if (xdi[s] >= 0) xib[nb * XI_BUF + xdi[s]] = xv[s];
            __syncthreads();
        }
        cur ^= 1;
    }
}

// ---------------------------------------------------------------------------
extern "C" void kernel_launch(void* const* d_in, const int* in_sizes, int n_in,
                              void* d_out, int out_size)
{
    (void)in_sizes; (void)n_in; (void)out_size;
    const float* x  = (const float*)d_in[0];
    const float* w1 = (const float*)d_in[1];
    const float* b1 = (const float*)d_in[2];
    const float* w2 = (const float*)d_in[3];
    const float* b2 = (const float*)d_in[4];
    float* out = (float*)d_out;

    cudaFuncSetAttribute(k1_conv1x1,
                         cudaFuncAttributeMaxDynamicSharedMemorySize, SM1_TOTAL);
    k1_conv1x1<<<512, 256, SM1_TOTAL>>>(x, w1, b1);
    k2_encoder<<<dim3(4, 8, 8), 128>>>(w2, b2);
    k3_apply<<<dim3(4, 4, 32), 256>>>(x, out);
}